// round 13
// baseline (speedup 1.0000x reference)
#include <cuda_runtime.h>
#include <cuda_fp16.h>
#include <math.h>
#include <stdint.h>

#define B_ 8
#define N_ 2048
#define FIN 128
#define FOUT 64
#define NNODE (B_*N_)

#define SPLIT 2
#define JCH (N_/SPLIT)      // 1024
#define BK 64
#define NST (JCH/BK)        // 16
#define BM 64               // rows per CTA (halved: occupancy 3)

// ---- gat smem (fp16 units) ----
#define PSTRB 72                      // 144B row stride (conflict-free ldmatrix/LDS)
#define PBUFB (BM*PSTRB)              // 4608
#define BROWS 72                      // 64 Wh cols + 8 ones/zeros rows
#define BBUFB (BROWS*PSTRB)           // 5184
#define OFF_P0 0
#define OFF_P1 PBUFB
#define OFF_B0 (2*PBUFB)
#define OFF_B1 (2*PBUFB + BBUFB)
#define GAT_SMEM ((2*PBUFB + 2*BBUFB)*2)   // 39168 B

// ---- prep smem (float units): single-tf32 W ----
#define HSTR 132
#define WSTR 72
#define PREP_SMEM ((64*HSTR + FIN*WSTR + 128 + 256)*4)   // 72192 B

// ---------------- scratch ----------------------------------------------------
__device__ __half g_WhT[(size_t)B_*FOUT*N_];    // [b][col][k] fp16
__device__ float g_f1[NNODE], g_f2[NNODE];
__device__ float g_E1p[NNODE], g_E1n[NNODE];    // row-rescaled
__device__ float g_E2p[NNODE], g_E2n[NNODE];
__device__ float g_acc[(size_t)SPLIT*NNODE*FOUT];
__device__ float g_Z[(size_t)SPLIT*NNODE];

// ---------------- helpers ----------------------------------------------------
__device__ __forceinline__ uint32_t smem_u32(const void* p) {
    uint32_t a;
    asm("{ .reg .u64 t; cvta.to.shared.u64 t, %1; cvt.u32.u64 %0, t; }" : "=r"(a) : "l"(p));
    return a;
}
__device__ __forceinline__ float cvt_tf32(float x) {
    uint32_t u;
    asm("cvt.rna.tf32.f32 %0, %1;" : "=r"(u) : "f"(x));
    return __uint_as_float(u);
}
__device__ __forceinline__ void cp16(uint32_t dst, const void* src) {
    asm volatile("cp.async.cg.shared.global [%0], [%1], 16;" :: "r"(dst), "l"(src));
}
#define CP_COMMIT() asm volatile("cp.async.commit_group;" ::: "memory")
#define CP_WAIT0()  asm volatile("cp.async.wait_group 0;" ::: "memory")

__device__ __forceinline__ uint32_t packh2(float lo, float hi) {
    __half2 h = __floats2half2_rn(lo, hi);
    return *reinterpret_cast<uint32_t*>(&h);
}

#define MMA_TF32(D, A0, A1, A2, A3, Bb0, Bb1)                                   \
    asm("mma.sync.aligned.m16n8k8.row.col.f32.tf32.tf32.f32 "                   \
        "{%0,%1,%2,%3}, {%4,%5,%6,%7}, {%8,%9}, {%0,%1,%2,%3};"                 \
        : "+f"((D)[0]), "+f"((D)[1]), "+f"((D)[2]), "+f"((D)[3])                \
        : "r"(A0), "r"(A1), "r"(A2), "r"(A3), "r"(Bb0), "r"(Bb1))

#define MMA_F16(D, Aa, Bb0, Bb1)                                                \
    asm("mma.sync.aligned.m16n8k16.row.col.f32.f16.f16.f32 "                    \
        "{%0,%1,%2,%3}, {%4,%5,%6,%7}, {%8,%9}, {%0,%1,%2,%3};"                 \
        : "+f"((D)[0]), "+f"((D)[1]), "+f"((D)[2]), "+f"((D)[3])                \
        : "r"((Aa)[0]), "r"((Aa)[1]), "r"((Aa)[2]), "r"((Aa)[3]),               \
          "r"(Bb0), "r"(Bb1))

#define LDMATRIX_X4(Aa, addr)                                                   \
    asm volatile("ldmatrix.sync.aligned.m8n8.x4.shared.b16 {%0,%1,%2,%3}, [%4];"\
        : "=r"((Aa)[0]), "=r"((Aa)[1]), "=r"((Aa)[2]), "=r"((Aa)[3])            \
        : "r"(addr))

// ---------------------------------------------------------------------------
// Prep (R12 verbatim): 64-row CTAs, single-tf32 W, smem transpose epilogue.
// ---------------------------------------------------------------------------
__global__ void __launch_bounds__(256) prep_mma(const float* __restrict__ h,
                                                const float* __restrict__ W,
                                                const float* __restrict__ a) {
    extern __shared__ float sp_[];
    float* hs  = sp_;                        // [64][132]
    float* WsH = hs + 64*HSTR;               // [128][72]
    float* as_ = WsH + FIN*WSTR;             // [128]
    float* f1p = as_ + 128;                  // [2][64]
    float* f2p = f1p + 128;                  // [2][64]

    const int tid = threadIdx.x;
    const int i0 = blockIdx.x * 64;

    if (tid < 128) as_[tid] = a[tid];

#pragma unroll
    for (int it = 0; it < 8; it++) {
        const int lin = it*256 + tid;
        const int k = lin >> 4, c4 = (lin & 15) * 4;
        const float4 w = *(const float4*)(W + k*FOUT + c4);
        *(float4*)(WsH + k*WSTR + c4) =
            make_float4(cvt_tf32(w.x), cvt_tf32(w.y), cvt_tf32(w.z), cvt_tf32(w.w));
    }
#pragma unroll
    for (int it = 0; it < 8; it++) {
        const int lin = it*256 + tid;
        const int r = lin >> 5, c = (lin & 31) * 4;
        *(float4*)(hs + r*HSTR + c) = *(const float4*)(h + (size_t)(i0 + r)*FIN + c);
    }
    __syncthreads();

    const int wid = tid >> 5, lane = tid & 31;
    const int gid = lane >> 2, tig = lane & 3;
    const int mt4 = wid & 3;
    const int nh = wid >> 2;

    float acc[4][4] = {};
    const float* Ap = hs + (mt4*16 + gid)*HSTR + tig;
    const float* BH = WsH + tig*WSTR + nh*32 + gid;

#pragma unroll
    for (int kq = 0; kq < 16; kq++) {
        const uint32_t A0 = __float_as_uint(cvt_tf32(Ap[kq*8]));
        const uint32_t A1 = __float_as_uint(cvt_tf32(Ap[kq*8 + 8*HSTR]));
        const uint32_t A2 = __float_as_uint(cvt_tf32(Ap[kq*8 + 4]));
        const uint32_t A3 = __float_as_uint(cvt_tf32(Ap[kq*8 + 4 + 8*HSTR]));
        const float* bh = BH + kq*8*WSTR;
#pragma unroll
        for (int nt = 0; nt < 4; nt++) {
            const uint32_t bh0 = __float_as_uint(bh[nt*8]);
            const uint32_t bh1 = __float_as_uint(bh[nt*8 + 4*WSTR]);
            MMA_TF32(acc[nt], A0, A1, A2, A3, bh0, bh1);
        }
    }

    float f1a = 0.f, f2a = 0.f, f1b = 0.f, f2b = 0.f;
#pragma unroll
    for (int nt = 0; nt < 4; nt++) {
        const int c = nh*32 + nt*8 + tig*2;
        const float a10 = as_[c], a11 = as_[c+1];
        const float a20 = as_[64+c], a21 = as_[64+c+1];
        f1a += acc[nt][0]*a10 + acc[nt][1]*a11;
        f2a += acc[nt][0]*a20 + acc[nt][1]*a21;
        f1b += acc[nt][2]*a10 + acc[nt][3]*a11;
        f2b += acc[nt][2]*a20 + acc[nt][3]*a21;
    }
#pragma unroll
    for (int o = 1; o <= 2; o <<= 1) {
        f1a += __shfl_xor_sync(0xffffffffu, f1a, o);
        f2a += __shfl_xor_sync(0xffffffffu, f2a, o);
        f1b += __shfl_xor_sync(0xffffffffu, f1b, o);
        f2b += __shfl_xor_sync(0xffffffffu, f2b, o);
    }
    if (tig == 0) {
        const int ri = mt4*16 + gid;
        f1p[nh*64 + ri] = f1a;   f1p[nh*64 + ri + 8] = f1b;
        f2p[nh*64 + ri] = f2a;   f2p[nh*64 + ri + 8] = f2b;
    }
    __syncthreads();

    __half* Wt = (__half*)sp_;               // aliases hs (GEMM reads done)
#pragma unroll
    for (int nt = 0; nt < 4; nt++) {
#pragma unroll
        for (int e = 0; e < 4; e++) {
            const int col = nh*32 + nt*8 + tig*2 + (e & 1);
            const int kl = mt4*16 + gid + ((e >> 1) << 3);
            Wt[col*72 + kl] = __float2half(acc[nt][e]);
        }
    }
    __syncthreads();

    const int bb = i0 >> 11;
    const int kbase = i0 & (N_-1);
    {
        const int col = tid >> 2, seg = tid & 3;
        const __half* srcw = Wt + col*72 + seg*16;
        __half* dstw = g_WhT + (size_t)bb*FOUT*N_ + (size_t)col*N_ + kbase + seg*16;
        *(uint4*)dstw = *(const uint4*)srcw;
        *(uint4*)(dstw + 8) = *(const uint4*)(srcw + 8);
    }
    if (tid < 64) {
        g_f1[i0 + tid] = f1p[tid] + f1p[64 + tid];
        g_f2[i0 + tid] = f2p[tid] + f2p[64 + tid];
    }
}

// ---------------------------------------------------------------------------
__global__ void __launch_bounds__(256) scalars_kernel() {
    __shared__ float red[8];
    __shared__ float M2s;
    const int b = blockIdx.x, tid = threadIdx.x;
    const int base = b * N_;

    float m = -1e30f;
#pragma unroll
    for (int k = 0; k < 8; k++) m = fmaxf(m, g_f2[base + tid + k*256]);
#pragma unroll
    for (int o = 16; o > 0; o >>= 1) m = fmaxf(m, __shfl_xor_sync(0xffffffffu, m, o));
    if ((tid & 31) == 0) red[tid >> 5] = m;
    __syncthreads();
    if (tid == 0) {
        float mm = red[0];
#pragma unroll
        for (int i = 1; i < 8; i++) mm = fmaxf(mm, red[i]);
        M2s = mm;
    }
    __syncthreads();
    const float M2 = M2s;

#pragma unroll
    for (int k = 0; k < 8; k++) {
        const int node = base + tid + k*256;
        const float f1 = g_f1[node], f2 = g_f2[node];
        const float S = f1 + M2;
        const float mi = (S >= 0.f) ? S : 0.2f*S;
        g_E1p[node] = expf(f1 - mi);
        g_E1n[node] = expf(0.2f*f1 - mi);
        g_E2p[node] = expf(f2);
        g_E2n[node] = expf(0.2f*f2);
    }
}

// ---------------------------------------------------------------------------
// Main v4: CTA = (64 rows, batch, 1024-j chunk); 16 stages BK=64; occ 3.
// Same structure as R7/R12 gat but BM=64: warp = 1 m16 tile x n-half;
// P-build thread covers 2 rows x 8 cols.
// ---------------------------------------------------------------------------
__global__ void __launch_bounds__(256,3) gat_mma(const int* __restrict__ adj) {
    extern __shared__ __half smb[];
    const uint32_t sb = smem_u32(smb);
    const int tid = threadIdx.x;
    const int b  = blockIdx.y;
    const int sp = blockIdx.z;
    const int i0 = blockIdx.x * BM;
    const int js = sp * JCH;
    const int nodeBase = b * N_;

    const int rg = tid >> 3;          // P rows rg*2..+1 (0..31)
    const int cg = tid & 7;           // P cols cg*8..+7
    const int wid = tid >> 5, lane = tid & 31;
    const int gid = lane >> 2, tig = lane & 3;
    const int mt = wid & 3;           // m16 tile (rows mt*16..+15)
    const int nw = wid >> 2;          // n-half

    // row scalars (2 rows per thread)
    const int nd0 = nodeBase + i0 + rg*2;
    const float e1p0 = g_E1p[nd0],   e1n0 = g_E1n[nd0];
    const float e1p1 = g_E1p[nd0+1], e1n1 = g_E1n[nd0+1];

    // ones/zeros rows 64..71 of both B buffers
    for (int idx = tid; idx < 2*8*PSTRB; idx += 256) {
        const int buf = idx / (8*PSTRB);
        const int rem = idx - buf*(8*PSTRB);
        const int rr = rem / PSTRB, cc = rem - rr*PSTRB;
        smb[(buf ? OFF_B1 : OFF_B0) + (64 + rr)*PSTRB + cc] =
            (rr == 0 && cc < 64) ? __float2half(1.0f) : __float2half(0.0f);
    }

    // B staging (identical to R12): 64 rows x 128B via 2 cp16/thread
    const int brow = tid >> 3, bseg = (tid & 7) * 8;
    const __half* bsrc = g_WhT + (size_t)b*FOUT*N_ + (size_t)brow*N_ + js + bseg;

#define CPB(S) do {                                                              \
        const uint32_t _bo = ((S)&1) ? OFF_B1 : OFF_B0;                          \
        cp16(sb + (_bo + brow*PSTRB + bseg)*2,        bsrc + (S)*BK);            \
        cp16(sb + (_bo + (brow+32)*PSTRB + bseg)*2,   bsrc + (size_t)32*N_ + (S)*BK); \
        CP_COMMIT();                                                             \
    } while (0)

    const int* adjR0 = adj + (size_t)b*N_*N_ + (size_t)(i0 + rg*2)*N_ + js + cg*8;
    int4 a4[4];                       // 2 rows x 2 int4
    float4 p2v0, p2v1, n2v0, n2v1;    // 8 cols of E2p/E2n

#define PF(S) do {                                                               \
        a4[0] = __ldcs((const int4*)(adjR0 + (S)*BK));                           \
        a4[1] = __ldcs((const int4*)(adjR0 + (S)*BK + 4));                       \
        a4[2] = __ldcs((const int4*)(adjR0 + (size_t)N_ + (S)*BK));              \
        a4[3] = __ldcs((const int4*)(adjR0 + (size_t)N_ + (S)*BK + 4));          \
        const int _cn = nodeBase + js + (S)*BK + cg*8;                           \
        p2v0 = *(const float4*)(g_E2p + _cn);                                    \
        p2v1 = *(const float4*)(g_E2p + _cn + 4);                                \
        n2v0 = *(const float4*)(g_E2n + _cn);                                    \
        n2v1 = *(const float4*)(g_E2n + _cn + 4);                                \
    } while (0)

    CPB(0);
    PF(0);

    const uint32_t aoff = ((uint32_t)((mt*16 + (lane & 7) + ((lane >> 3) & 1)*8)*PSTRB
                           + (lane >> 4)*8)) * 2;

    float acc[4][4] = {};
    float accZ[4] = {};

    for (int s = 0; s < NST; s++) {
        const uint32_t pOff = (s & 1) ? OFF_P1 : OFF_P0;
        const float p2a[8] = {p2v0.x, p2v0.y, p2v0.z, p2v0.w,
                              p2v1.x, p2v1.y, p2v1.z, p2v1.w};
        const float n2a[8] = {n2v0.x, n2v0.y, n2v0.z, n2v0.w,
                              n2v1.x, n2v1.y, n2v1.z, n2v1.w};

        // ---- P build: 2 rows x 8 cols -> 2 STS.128 ----
#pragma unroll
        for (int rr = 0; rr < 2; rr++) {
            const float e1p = rr ? e1p1 : e1p0;
            const float e1n = rr ? e1n1 : e1n0;
            const int am4[8] = {a4[rr*2].x, a4[rr*2].y, a4[rr*2].z, a4[rr*2].w,
                                a4[rr*2+1].x, a4[rr*2+1].y, a4[rr*2+1].z, a4[rr*2+1].w};
            float pv[8];
#pragma unroll
            for (int c = 0; c < 8; c++) {
                const float v = fmaxf(e1p*p2a[c], e1n*n2a[c]);
                pv[c] = (am4[c] != 0) ? v : 0.f;
            }
            uint4 pk;
            pk.x = packh2(pv[0], pv[1]);
            pk.y = packh2(pv[2], pv[3]);
            pk.z = packh2(pv[4], pv[5]);
            pk.w = packh2(pv[6], pv[7]);
            *(uint4*)(smb + pOff + (rg*2 + rr)*PSTRB + cg*8) = pk;
        }

        if (s + 1 < NST) PF(s + 1);     // adj LDG issue right after last use

        CP_WAIT0();                     // B(s) landed
        __syncthreads();                // P(s)+B(s) visible; prev GEMM done
        if (s + 1 < NST) CPB(s + 1);

        // ---- GEMM: 4 kq x (1 ldmatrix + 4 nt + ones) ----
        const uint32_t pB = sb + pOff*2;
        const __half* Bs = smb + ((s & 1) ? OFF_B1 : OFF_B0);
#pragma unroll
        for (int kq = 0; kq < 4; kq++) {
            uint32_t A[4];
            LDMATRIX_X4(A, pB + aoff + kq*32);
            const __half* Bk = Bs + kq*16 + tig*2;
#pragma unroll
            for (int nt = 0; nt < 4; nt++) {
                const int nrow = nw*32 + nt*8 + gid;
                const uint32_t b0 = *(const uint32_t*)(Bk + nrow*PSTRB);
                const uint32_t b1 = *(const uint32_t*)(Bk + nrow*PSTRB + 8);
                MMA_F16(acc[nt], A, b0, b1);
            }
            if (nw == 1) {
                const uint32_t bo0 = *(const uint32_t*)(Bk + (64+gid)*PSTRB);
                const uint32_t bo1 = *(const uint32_t*)(Bk + (64+gid)*PSTRB + 8);
                MMA_F16(accZ, A, bo0, bo1);
            }
        }
    }

    // ---- store partials ----
    const size_t obase = ((size_t)sp*NNODE + nodeBase + i0) * FOUT;
    const int row = mt*16 + gid;
#pragma unroll
    for (int nt = 0; nt < 4; nt++) {
        const int col = nw*32 + nt*8 + tig*2;
        *(float2*)&g_acc[obase + (size_t)row*FOUT + col] =
            make_float2(acc[nt][0], acc[nt][1]);
        *(float2*)&g_acc[obase + (size_t)(row + 8)*FOUT + col] =
            make_float2(acc[nt][2], acc[nt][3]);
    }
    if (nw == 1 && tig == 0) {
        g_Z[(size_t)sp*NNODE + nodeBase + i0 + row]     = accZ[0];
        g_Z[(size_t)sp*NNODE + nodeBase + i0 + row + 8] = accZ[2];
    }
}

// ---------------------------------------------------------------------------
__global__ void __launch_bounds__(256) combine_kernel(float* __restrict__ out) {
    const int idx = blockIdx.x * 256 + threadIdx.x;   // 0 .. NNODE*8-1
    const int node = idx >> 3;
    const int f8 = (idx & 7) * 8;
    float s0x=0.f,s0y=0.f,s0z=0.f,s0w=0.f;
    float s1x=0.f,s1y=0.f,s1z=0.f,s1w=0.f;
    float z = 0.f;
#pragma unroll
    for (int sp = 0; sp < SPLIT; sp++) {
        const float* base = &g_acc[((size_t)sp*NNODE + node)*FOUT + f8];
        const float4 v0 = *(const float4*)base;
        const float4 v1 = *(const float4*)(base + 4);
        s0x += v0.x; s0y += v0.y; s0z += v0.z; s0w += v0.w;
        s1x += v1.x; s1y += v1.y; s1z += v1.z; s1w += v1.w;
        z += g_Z[(size_t)sp*NNODE + node];
    }
    const float inv = 1.0f / z;
    float* op = &out[(size_t)node*FOUT + f8];
    *(float4*)op       = make_float4(s0x*inv, s0y*inv, s0z*inv, s0w*inv);
    *(float4*)(op + 4) = make_float4(s1x*inv, s1y*inv, s1z*inv, s1w*inv);
}

// ---------------------------------------------------------------------------
extern "C" void kernel_launch(void* const* d_in, const int* in_sizes, int n_in,
                              void* d_out, int out_size) {
    const float* h   = (const float*)d_in[0];
    const float* W   = (const float*)d_in[1];
    const float* a   = (const float*)d_in[2];
    const int*   adj = (const int*)d_in[3];
    float* out = (float*)d_out;

    cudaFuncSetAttribute(prep_mma, cudaFuncAttributeMaxDynamicSharedMemorySize, PREP_SMEM);
    prep_mma<<<NNODE/64, 256, PREP_SMEM>>>(h, W, a);

    scalars_kernel<<<B_, 256>>>();

    cudaFuncSetAttribute(gat_mma, cudaFuncAttributeMaxDynamicSharedMemorySize, GAT_SMEM);
    dim3 grid(N_/BM, B_, SPLIT);
    gat_mma<<<grid, 256, GAT_SMEM>>>(adj);

    combine_kernel<<<(NNODE*8)/256, 256>>>(out);
}

// round 15
// speedup vs baseline: 1.1120x; 1.1120x over previous
#include <cuda_runtime.h>
#include <cuda_fp16.h>
#include <math.h>
#include <stdint.h>

#define B_ 8
#define N_ 2048
#define FIN 128
#define FOUT 64
#define NNODE (B_*N_)

#define SPLIT 2
#define JCH (N_/SPLIT)      // 1024
#define BK 64
#define NST (JCH/BK)        // 16
#define BM 128

// ---- gat smem (fp16 units) ---- (R12 layout, verbatim)
#define PSTRB 72                      // 144B row stride (conflict-free ldmatrix/LDS)
#define PBUFB (BM*PSTRB)              // 9216
#define BROWS 72                      // 64 Wh cols + 8 ones/zeros rows
#define BBUFB (BROWS*PSTRB)           // 5184
#define OFF_P0 0
#define OFF_P1 PBUFB
#define OFF_B0 (2*PBUFB)
#define OFF_B1 (2*PBUFB + BBUFB)
#define GAT_SMEM ((2*PBUFB + 2*BBUFB)*2)   // 57600 B

// ---- prep smem (float units): single-tf32 W ----
#define HSTR 132
#define WSTR 72
#define PREP_SMEM ((64*HSTR + FIN*WSTR + 128 + 256)*4)   // 72192 B

// ---------------- scratch ----------------------------------------------------
__device__ __half g_WhT[(size_t)B_*FOUT*N_];    // [b][col][k] fp16
__device__ float g_f1[NNODE], g_f2[NNODE];
__device__ float g_E1p[NNODE], g_E1n[NNODE];    // row-rescaled
__device__ float g_E2p[NNODE], g_E2n[NNODE];
__device__ float g_acc[(size_t)SPLIT*NNODE*FOUT];
__device__ float g_Z[(size_t)SPLIT*NNODE];
__device__ int   g_cnt[B_*(N_/BM)];             // 128 tickets (zero-init; reset by finalizer)

// ---------------- helpers ----------------------------------------------------
__device__ __forceinline__ uint32_t smem_u32(const void* p) {
    uint32_t a;
    asm("{ .reg .u64 t; cvta.to.shared.u64 t, %1; cvt.u32.u64 %0, t; }" : "=r"(a) : "l"(p));
    return a;
}
__device__ __forceinline__ float cvt_tf32(float x) {
    uint32_t u;
    asm("cvt.rna.tf32.f32 %0, %1;" : "=r"(u) : "f"(x));
    return __uint_as_float(u);
}
__device__ __forceinline__ void cp16(uint32_t dst, const void* src) {
    asm volatile("cp.async.cg.shared.global [%0], [%1], 16;" :: "r"(dst), "l"(src));
}
#define CP_COMMIT() asm volatile("cp.async.commit_group;" ::: "memory")
#define CP_WAIT0()  asm volatile("cp.async.wait_group 0;" ::: "memory")

#define MMA_TF32(D, A0, A1, A2, A3, Bb0, Bb1)                                   \
    asm("mma.sync.aligned.m16n8k8.row.col.f32.tf32.tf32.f32 "                   \
        "{%0,%1,%2,%3}, {%4,%5,%6,%7}, {%8,%9}, {%0,%1,%2,%3};"                 \
        : "+f"((D)[0]), "+f"((D)[1]), "+f"((D)[2]), "+f"((D)[3])                \
        : "r"(A0), "r"(A1), "r"(A2), "r"(A3), "r"(Bb0), "r"(Bb1))

#define MMA_F16(D, Aa, Bb0, Bb1)                                                \
    asm("mma.sync.aligned.m16n8k16.row.col.f32.f16.f16.f32 "                    \
        "{%0,%1,%2,%3}, {%4,%5,%6,%7}, {%8,%9}, {%0,%1,%2,%3};"                 \
        : "+f"((D)[0]), "+f"((D)[1]), "+f"((D)[2]), "+f"((D)[3])                \
        : "r"((Aa)[0]), "r"((Aa)[1]), "r"((Aa)[2]), "r"((Aa)[3]),               \
          "r"(Bb0), "r"(Bb1))

#define LDMATRIX_X4(Aa, addr)                                                   \
    asm volatile("ldmatrix.sync.aligned.m8n8.x4.shared.b16 {%0,%1,%2,%3}, [%4];"\
        : "=r"((Aa)[0]), "=r"((Aa)[1]), "=r"((Aa)[2]), "=r"((Aa)[3])            \
        : "r"(addr))

// ---------------------------------------------------------------------------
// Prep (R12 verbatim): 64-row CTAs, single-tf32 W, smem transpose epilogue.
// ---------------------------------------------------------------------------
__global__ void __launch_bounds__(256) prep_mma(const float* __restrict__ h,
                                                const float* __restrict__ W,
                                                const float* __restrict__ a) {
    extern __shared__ float sp_[];
    float* hs  = sp_;                        // [64][132]
    float* WsH = hs + 64*HSTR;               // [128][72]
    float* as_ = WsH + FIN*WSTR;             // [128]
    float* f1p = as_ + 128;                  // [2][64]
    float* f2p = f1p + 128;                  // [2][64]

    const int tid = threadIdx.x;
    const int i0 = blockIdx.x * 64;

    if (tid < 128) as_[tid] = a[tid];

#pragma unroll
    for (int it = 0; it < 8; it++) {
        const int lin = it*256 + tid;
        const int k = lin >> 4, c4 = (lin & 15) * 4;
        const float4 w = *(const float4*)(W + k*FOUT + c4);
        *(float4*)(WsH + k*WSTR + c4) =
            make_float4(cvt_tf32(w.x), cvt_tf32(w.y), cvt_tf32(w.z), cvt_tf32(w.w));
    }
#pragma unroll
    for (int it = 0; it < 8; it++) {
        const int lin = it*256 + tid;
        const int r = lin >> 5, c = (lin & 31) * 4;
        *(float4*)(hs + r*HSTR + c) = *(const float4*)(h + (size_t)(i0 + r)*FIN + c);
    }
    __syncthreads();

    const int wid = tid >> 5, lane = tid & 31;
    const int gid = lane >> 2, tig = lane & 3;
    const int mt4 = wid & 3;
    const int nh = wid >> 2;

    float acc[4][4] = {};
    const float* Ap = hs + (mt4*16 + gid)*HSTR + tig;
    const float* BH = WsH + tig*WSTR + nh*32 + gid;

#pragma unroll
    for (int kq = 0; kq < 16; kq++) {
        const uint32_t A0 = __float_as_uint(cvt_tf32(Ap[kq*8]));
        const uint32_t A1 = __float_as_uint(cvt_tf32(Ap[kq*8 + 8*HSTR]));
        const uint32_t A2 = __float_as_uint(cvt_tf32(Ap[kq*8 + 4]));
        const uint32_t A3 = __float_as_uint(cvt_tf32(Ap[kq*8 + 4 + 8*HSTR]));
        const float* bh = BH + kq*8*WSTR;
#pragma unroll
        for (int nt = 0; nt < 4; nt++) {
            const uint32_t bh0 = __float_as_uint(bh[nt*8]);
            const uint32_t bh1 = __float_as_uint(bh[nt*8 + 4*WSTR]);
            MMA_TF32(acc[nt], A0, A1, A2, A3, bh0, bh1);
        }
    }

    float f1a = 0.f, f2a = 0.f, f1b = 0.f, f2b = 0.f;
#pragma unroll
    for (int nt = 0; nt < 4; nt++) {
        const int c = nh*32 + nt*8 + tig*2;
        const float a10 = as_[c], a11 = as_[c+1];
        const float a20 = as_[64+c], a21 = as_[64+c+1];
        f1a += acc[nt][0]*a10 + acc[nt][1]*a11;
        f2a += acc[nt][0]*a20 + acc[nt][1]*a21;
        f1b += acc[nt][2]*a10 + acc[nt][3]*a11;
        f2b += acc[nt][2]*a20 + acc[nt][3]*a21;
    }
#pragma unroll
    for (int o = 1; o <= 2; o <<= 1) {
        f1a += __shfl_xor_sync(0xffffffffu, f1a, o);
        f2a += __shfl_xor_sync(0xffffffffu, f2a, o);
        f1b += __shfl_xor_sync(0xffffffffu, f1b, o);
        f2b += __shfl_xor_sync(0xffffffffu, f2b, o);
    }
    if (tig == 0) {
        const int ri = mt4*16 + gid;
        f1p[nh*64 + ri] = f1a;   f1p[nh*64 + ri + 8] = f1b;
        f2p[nh*64 + ri] = f2a;   f2p[nh*64 + ri + 8] = f2b;
    }
    __syncthreads();

    __half* Wt = (__half*)sp_;               // aliases hs (GEMM reads done)
#pragma unroll
    for (int nt = 0; nt < 4; nt++) {
#pragma unroll
        for (int e = 0; e < 4; e++) {
            const int col = nh*32 + nt*8 + tig*2 + (e & 1);
            const int kl = mt4*16 + gid + ((e >> 1) << 3);
            Wt[col*72 + kl] = __float2half(acc[nt][e]);
        }
    }
    __syncthreads();

    const int bb = i0 >> 11;
    const int kbase = i0 & (N_-1);
    {
        const int col = tid >> 2, seg = tid & 3;
        const __half* srcw = Wt + col*72 + seg*16;
        __half* dstw = g_WhT + (size_t)bb*FOUT*N_ + (size_t)col*N_ + kbase + seg*16;
        *(uint4*)dstw = *(const uint4*)srcw;
        *(uint4*)(dstw + 8) = *(const uint4*)(srcw + 8);
    }
    if (tid < 64) {
        g_f1[i0 + tid] = f1p[tid] + f1p[64 + tid];
        g_f2[i0 + tid] = f2p[tid] + f2p[64 + tid];
    }
}

// ---------------------------------------------------------------------------
__global__ void __launch_bounds__(256) scalars_kernel() {
    __shared__ float red[8];
    __shared__ float M2s;
    const int b = blockIdx.x, tid = threadIdx.x;
    const int base = b * N_;

    float m = -1e30f;
#pragma unroll
    for (int k = 0; k < 8; k++) m = fmaxf(m, g_f2[base + tid + k*256]);
#pragma unroll
    for (int o = 16; o > 0; o >>= 1) m = fmaxf(m, __shfl_xor_sync(0xffffffffu, m, o));
    if ((tid & 31) == 0) red[tid >> 5] = m;
    __syncthreads();
    if (tid == 0) {
        float mm = red[0];
#pragma unroll
        for (int i = 1; i < 8; i++) mm = fmaxf(mm, red[i]);
        M2s = mm;
    }
    __syncthreads();
    const float M2 = M2s;

#pragma unroll
    for (int k = 0; k < 8; k++) {
        const int node = base + tid + k*256;
        const float f1 = g_f1[node], f2 = g_f2[node];
        const float S = f1 + M2;
        const float mi = (S >= 0.f) ? S : 0.2f*S;
        g_E1p[node] = expf(f1 - mi);
        g_E1n[node] = expf(0.2f*f1 - mi);
        g_E2p[node] = expf(f2);
        g_E2n[node] = expf(0.2f*f2);
    }
}

// ---------------------------------------------------------------------------
// Main (R12 loop verbatim) + fused finalize: the second CTA of each (b,i0)
// pair (atomic ticket) adds the peer's partial to its register accumulators,
// divides by summed Z, and writes out directly. Combine kernel eliminated.
// ---------------------------------------------------------------------------
__global__ void __launch_bounds__(256,2) gat_mma(const int* __restrict__ adj,
                                                 float* __restrict__ out) {
    extern __shared__ __half smb[];
    const uint32_t sb = smem_u32(smb);
    const int tid = threadIdx.x;
    const int b  = blockIdx.y;
    const int sp = blockIdx.z;
    const int i0 = blockIdx.x * BM;
    const int js = sp * JCH;
    const int nodeBase = b * N_;

    const int rg = tid >> 4;          // P rows rg*8..+7
    const int cg = tid & 15;          // P cols cg*4..+3 (within BK)
    const int wid = tid >> 5, lane = tid & 31;
    const int gid = lane >> 2, tig = lane & 3;
    const int am = (wid & 3) * 32;    // warp m-offset (2 m16 tiles)
    const int nw = wid >> 2;          // warp n-half

    float e1p[8], e1n[8];
#pragma unroll
    for (int r = 0; r < 8; r++) {
        const int node = nodeBase + i0 + rg*8 + r;
        e1p[r] = g_E1p[node];
        e1n[r] = g_E1n[node];
    }

    // ones/zeros rows 64..71 of both B buffers
    for (int idx = tid; idx < 2*8*PSTRB; idx += 256) {
        const int buf = idx / (8*PSTRB);
        const int rem = idx - buf*(8*PSTRB);
        const int rr = rem / PSTRB, cc = rem - rr*PSTRB;
        smb[(buf ? OFF_B1 : OFF_B0) + (64 + rr)*PSTRB + cc] =
            (rr == 0 && cc < 64) ? __float2half(1.0f) : __float2half(0.0f);
    }

    // B staging: 64 rows x 128B; thread covers (row tid>>3, seg tid&7), 2 passes
    const int brow = tid >> 3, bseg = (tid & 7) * 8;
    const __half* bsrc = g_WhT + (size_t)b*FOUT*N_ + (size_t)brow*N_ + js + bseg;

#define CPB(S) do {                                                              \
        const uint32_t _bo = ((S)&1) ? OFF_B1 : OFF_B0;                          \
        cp16(sb + (_bo + brow*PSTRB + bseg)*2,        bsrc + (S)*BK);            \
        cp16(sb + (_bo + (brow+32)*PSTRB + bseg)*2,   bsrc + (size_t)32*N_ + (S)*BK); \
        CP_COMMIT();                                                             \
    } while (0)

    const int* adjB = adj + (size_t)b*N_*N_ + (size_t)(i0 + rg*8)*N_ + js + cg*4;
    int4 a4[8]; float4 p2v, n2v;

#define PF(S) do {                                                               \
        _Pragma("unroll")                                                        \
        for (int r = 0; r < 8; r++)                                              \
            a4[r] = __ldcs((const int4*)(adjB + (size_t)r*N_ + (S)*BK));         \
        const int _cn = nodeBase + js + (S)*BK + cg*4;                           \
        p2v = *(const float4*)(g_E2p + _cn);                                     \
        n2v = *(const float4*)(g_E2n + _cn);                                     \
    } while (0)

    CPB(0);
    PF(0);

    uint32_t aoff[2];
#pragma unroll
    for (int mt = 0; mt < 2; mt++)
        aoff[mt] = ((am + mt*16 + (lane & 7) + ((lane >> 3) & 1)*8)*PSTRB
                    + (lane >> 4)*8) * 2;

    float acc[2][4][4] = {};
    float accZ[2][4] = {};

    for (int s = 0; s < NST; s++) {
        const uint32_t pOff = (s & 1) ? OFF_P1 : OFF_P0;
        const float p2a[4] = {p2v.x, p2v.y, p2v.z, p2v.w};
        const float n2a[4] = {n2v.x, n2v.y, n2v.z, n2v.w};

        // ---- P build (fp16, values <= 1) + STS.64 ----
#pragma unroll
        for (int r = 0; r < 8; r++) {
            const int am4[4] = {a4[r].x, a4[r].y, a4[r].z, a4[r].w};
            float pv[4];
#pragma unroll
            for (int c = 0; c < 4; c++) {
                const float v = fmaxf(e1p[r]*p2a[c], e1n[r]*n2a[c]);
                pv[c] = (am4[c] != 0) ? v : 0.f;
            }
            __half2 h01 = __floats2half2_rn(pv[0], pv[1]);
            __half2 h23 = __floats2half2_rn(pv[2], pv[3]);
            uint2 pk;
            pk.x = *reinterpret_cast<uint32_t*>(&h01);
            pk.y = *reinterpret_cast<uint32_t*>(&h23);
            *(uint2*)(smb + pOff + (rg*8 + r)*PSTRB + cg*4) = pk;
        }

        if (s + 1 < NST) PF(s + 1);     // issue adj LDG early

        CP_WAIT0();                     // B(s) landed
        __syncthreads();                // P(s)+B(s) visible; prev GEMM done
        if (s + 1 < NST) CPB(s + 1);

        // ---- GEMM: 4 kq x (2 ldmatrix + 4 nt + ones) ----
        const uint32_t pB = sb + pOff*2;
        const __half* Bs = smb + ((s & 1) ? OFF_B1 : OFF_B0);
#pragma unroll
        for (int kq = 0; kq < 4; kq++) {
            uint32_t A[2][4];
            LDMATRIX_X4(A[0], pB + aoff[0] + kq*32);
            LDMATRIX_X4(A[1], pB + aoff[1] + kq*32);
            const __half* Bk = Bs + kq*16 + tig*2;
#pragma unroll
            for (int nt = 0; nt < 4; nt++) {
                const int nrow = nw*32 + nt*8 + gid;
                const uint32_t b0 = *(const uint32_t*)(Bk + nrow*PSTRB);
                const uint32_t b1 = *(const uint32_t*)(Bk + nrow*PSTRB + 8);
                MMA_F16(acc[0][nt], A[0], b0, b1);
                MMA_F16(acc[1][nt], A[1], b0, b1);
            }
            if (nw == 1) {
                const uint32_t bo0 = *(const uint32_t*)(Bk + (64+gid)*PSTRB);
                const uint32_t bo1 = *(const uint32_t*)(Bk + (64+gid)*PSTRB + 8);
                MMA_F16(accZ[0], A[0], bo0, bo1);
                MMA_F16(accZ[1], A[1], bo0, bo1);
            }
        }
    }

    // ---- store partials (as R12) ----
    const size_t obase = ((size_t)sp*NNODE + nodeBase + i0) * FOUT;
#pragma unroll
    for (int mt = 0; mt < 2; mt++) {
        const int row = am + mt*16 + gid;
#pragma unroll
        for (int nt = 0; nt < 4; nt++) {
            const int col = nw*32 + nt*8 + tig*2;
            *(float2*)&g_acc[obase + (size_t)row*FOUT + col] =
                make_float2(acc[mt][nt][0], acc[mt][nt][1]);
            *(float2*)&g_acc[obase + (size_t)(row + 8)*FOUT + col] =
                make_float2(acc[mt][nt][2], acc[mt][nt][3]);
        }
        if (nw == 1 && tig == 0) {
            g_Z[(size_t)sp*NNODE + nodeBase + i0 + row]     = accZ[mt][0];
            g_Z[(size_t)sp*NNODE + nodeBase + i0 + row + 8] = accZ[mt][2];
        }
    }

    // ---- ticket rendezvous: second arriver finalizes ----
    __threadfence();
    __syncthreads();
    __shared__ int ticket_s;
    if (tid == 0) ticket_s = atomicAdd(&g_cnt[b*(N_/BM) + blockIdx.x], 1);
    __syncthreads();

    if (ticket_s == 1) {
        const size_t pbase = ((size_t)(1 - sp)*NNODE + nodeBase + i0) * FOUT;

        float inv[2][2];
#pragma unroll
        for (int mt = 0; mt < 2; mt++) {
            const int row = am + mt*16 + gid;
#pragma unroll
            for (int rr = 0; rr < 2; rr++) {
                const int r = nodeBase + i0 + row + rr*8;
                inv[mt][rr] = 1.0f / (g_Z[r] + g_Z[NNODE + r]);
            }
        }
#pragma unroll
        for (int mt = 0; mt < 2; mt++) {
            const int row = am + mt*16 + gid;
#pragma unroll
            for (int nt = 0; nt < 4; nt++) {
                const int col = nw*32 + nt*8 + tig*2;
                const float2 p0 = *(const float2*)&g_acc[pbase + (size_t)row*FOUT + col];
                const float2 p1 = *(const float2*)&g_acc[pbase + (size_t)(row + 8)*FOUT + col];
                *(float2*)&out[(size_t)(nodeBase + i0 + row)*FOUT + col] =
                    make_float2((acc[mt][nt][0] + p0.x)*inv[mt][0],
                                (acc[mt][nt][1] + p0.y)*inv[mt][0]);
                *(float2*)&out[(size_t)(nodeBase + i0 + row + 8)*FOUT + col] =
                    make_float2((acc[mt][nt][2] + p1.x)*inv[mt][1],
                                (acc[mt][nt][3] + p1.y)*inv[mt][1]);
            }
        }
        if (tid == 0) g_cnt[b*(N_/BM) + blockIdx.x] = 0;   // reset for next launch
    }
}

// ---------------------------------------------------------------------------
extern "C" void kernel_launch(void* const* d_in, const int* in_sizes, int n_in,
                              void* d_out, int out_size) {
    const float* h   = (const float*)d_in[0];
    const float* W   = (const float*)d_in[1];
    const float* a   = (const float*)d_in[2];
    const int*   adj = (const int*)d_in[3];
    float* out = (float*)d_out;

    cudaFuncSetAttribute(prep_mma, cudaFuncAttributeMaxDynamicSharedMemorySize, PREP_SMEM);
    prep_mma<<<NNODE/64, 256, PREP_SMEM>>>(h, W, a);

    scalars_kernel<<<B_, 256>>>();

    cudaFuncSetAttribute(gat_mma, cudaFuncAttributeMaxDynamicSharedMemorySize, GAT_SMEM);
    dim3 grid(N_/BM, B_, SPLIT);
    gat_mma<<<grid, 256, GAT_SMEM>>>(adj, out);
}

// round 16
// speedup vs baseline: 1.3014x; 1.1704x over previous
#include <cuda_runtime.h>
#include <cuda_fp16.h>
#include <math.h>
#include <stdint.h>

#define B_ 8
#define N_ 2048
#define FIN 128
#define FOUT 64
#define NNODE (B_*N_)

#define SPLIT 2
#define JCH (N_/SPLIT)      // 1024
#define BK 64
#define NST (JCH/BK)        // 16
#define BM 128

// ---- gat smem (fp16 units) ----
#define PSTRB 72                      // 144B row stride (conflict-free ldmatrix/LDS)
#define PBUFB (BM*PSTRB)              // 9216
#define BROWS 64                      // 64 Wh cols (ones rows removed)
#define BBUFB (BROWS*PSTRB)           // 4608
#define OFF_P0 0
#define OFF_P1 PBUFB
#define OFF_B0 (2*PBUFB)
#define OFF_B1 (2*PBUFB + BBUFB)
#define GAT_SMEM ((2*PBUFB + 2*BBUFB)*2)   // 55296 B

// ---- prep smem (float units): single-tf32 W ----
#define HSTR 132
#define WSTR 72
#define PREP_SMEM ((64*HSTR + FIN*WSTR + 128 + 256)*4)   // 72192 B

// ---------------- scratch ----------------------------------------------------
__device__ __half g_WhT[(size_t)B_*FOUT*N_];    // [b][col][k] fp16
__device__ float g_f1[NNODE], g_f2[NNODE];
__device__ float g_E1p[NNODE], g_E1n[NNODE];    // row-rescaled
__device__ float g_E2p[NNODE], g_E2n[NNODE];
__device__ float g_acc[(size_t)SPLIT*NNODE*FOUT];
__device__ float g_Z[(size_t)SPLIT*NNODE];

// ---------------- helpers ----------------------------------------------------
__device__ __forceinline__ uint32_t smem_u32(const void* p) {
    uint32_t a;
    asm("{ .reg .u64 t; cvta.to.shared.u64 t, %1; cvt.u32.u64 %0, t; }" : "=r"(a) : "l"(p));
    return a;
}
__device__ __forceinline__ float cvt_tf32(float x) {
    uint32_t u;
    asm("cvt.rna.tf32.f32 %0, %1;" : "=r"(u) : "f"(x));
    return __uint_as_float(u);
}
__device__ __forceinline__ void cp16(uint32_t dst, const void* src) {
    asm volatile("cp.async.cg.shared.global [%0], [%1], 16;" :: "r"(dst), "l"(src));
}
#define CP_COMMIT() asm volatile("cp.async.commit_group;" ::: "memory")
#define CP_WAIT0()  asm volatile("cp.async.wait_group 0;" ::: "memory")

#define MMA_TF32(D, A0, A1, A2, A3, Bb0, Bb1)                                   \
    asm("mma.sync.aligned.m16n8k8.row.col.f32.tf32.tf32.f32 "                   \
        "{%0,%1,%2,%3}, {%4,%5,%6,%7}, {%8,%9}, {%0,%1,%2,%3};"                 \
        : "+f"((D)[0]), "+f"((D)[1]), "+f"((D)[2]), "+f"((D)[3])                \
        : "r"(A0), "r"(A1), "r"(A2), "r"(A3), "r"(Bb0), "r"(Bb1))

#define MMA_F16(D, Aa, Bb0, Bb1)                                                \
    asm("mma.sync.aligned.m16n8k16.row.col.f32.f16.f16.f32 "                    \
        "{%0,%1,%2,%3}, {%4,%5,%6,%7}, {%8,%9}, {%0,%1,%2,%3};"                 \
        : "+f"((D)[0]), "+f"((D)[1]), "+f"((D)[2]), "+f"((D)[3])                \
        : "r"((Aa)[0]), "r"((Aa)[1]), "r"((Aa)[2]), "r"((Aa)[3]),               \
          "r"(Bb0), "r"(Bb1))

#define LDMATRIX_X4(Aa, addr)                                                   \
    asm volatile("ldmatrix.sync.aligned.m8n8.x4.shared.b16 {%0,%1,%2,%3}, [%4];"\
        : "=r"((Aa)[0]), "=r"((Aa)[1]), "=r"((Aa)[2]), "=r"((Aa)[3])            \
        : "r"(addr))

// ---------------------------------------------------------------------------
// Prep (R12 verbatim): 64-row CTAs, single-tf32 W, smem transpose epilogue.
// ---------------------------------------------------------------------------
__global__ void __launch_bounds__(256) prep_mma(const float* __restrict__ h,
                                                const float* __restrict__ W,
                                                const float* __restrict__ a) {
    extern __shared__ float sp_[];
    float* hs  = sp_;                        // [64][132]
    float* WsH = hs + 64*HSTR;               // [128][72]
    float* as_ = WsH + FIN*WSTR;             // [128]
    float* f1p = as_ + 128;                  // [2][64]
    float* f2p = f1p + 128;                  // [2][64]

    const int tid = threadIdx.x;
    const int i0 = blockIdx.x * 64;

    if (tid < 128) as_[tid] = a[tid];

#pragma unroll
    for (int it = 0; it < 8; it++) {
        const int lin = it*256 + tid;
        const int k = lin >> 4, c4 = (lin & 15) * 4;
        const float4 w = *(const float4*)(W + k*FOUT + c4);
        *(float4*)(WsH + k*WSTR + c4) =
            make_float4(cvt_tf32(w.x), cvt_tf32(w.y), cvt_tf32(w.z), cvt_tf32(w.w));
    }
#pragma unroll
    for (int it = 0; it < 8; it++) {
        const int lin = it*256 + tid;
        const int r = lin >> 5, c = (lin & 31) * 4;
        *(float4*)(hs + r*HSTR + c) = *(const float4*)(h + (size_t)(i0 + r)*FIN + c);
    }
    __syncthreads();

    const int wid = tid >> 5, lane = tid & 31;
    const int gid = lane >> 2, tig = lane & 3;
    const int mt4 = wid & 3;
    const int nh = wid >> 2;

    float acc[4][4] = {};
    const float* Ap = hs + (mt4*16 + gid)*HSTR + tig;
    const float* BH = WsH + tig*WSTR + nh*32 + gid;

#pragma unroll
    for (int kq = 0; kq < 16; kq++) {
        const uint32_t A0 = __float_as_uint(cvt_tf32(Ap[kq*8]));
        const uint32_t A1 = __float_as_uint(cvt_tf32(Ap[kq*8 + 8*HSTR]));
        const uint32_t A2 = __float_as_uint(cvt_tf32(Ap[kq*8 + 4]));
        const uint32_t A3 = __float_as_uint(cvt_tf32(Ap[kq*8 + 4 + 8*HSTR]));
        const float* bh = BH + kq*8*WSTR;
#pragma unroll
        for (int nt = 0; nt < 4; nt++) {
            const uint32_t bh0 = __float_as_uint(bh[nt*8]);
            const uint32_t bh1 = __float_as_uint(bh[nt*8 + 4*WSTR]);
            MMA_TF32(acc[nt], A0, A1, A2, A3, bh0, bh1);
        }
    }

    float f1a = 0.f, f2a = 0.f, f1b = 0.f, f2b = 0.f;
#pragma unroll
    for (int nt = 0; nt < 4; nt++) {
        const int c = nh*32 + nt*8 + tig*2;
        const float a10 = as_[c], a11 = as_[c+1];
        const float a20 = as_[64+c], a21 = as_[64+c+1];
        f1a += acc[nt][0]*a10 + acc[nt][1]*a11;
        f2a += acc[nt][0]*a20 + acc[nt][1]*a21;
        f1b += acc[nt][2]*a10 + acc[nt][3]*a11;
        f2b += acc[nt][2]*a20 + acc[nt][3]*a21;
    }
#pragma unroll
    for (int o = 1; o <= 2; o <<= 1) {
        f1a += __shfl_xor_sync(0xffffffffu, f1a, o);
        f2a += __shfl_xor_sync(0xffffffffu, f2a, o);
        f1b += __shfl_xor_sync(0xffffffffu, f1b, o);
        f2b += __shfl_xor_sync(0xffffffffu, f2b, o);
    }
    if (tig == 0) {
        const int ri = mt4*16 + gid;
        f1p[nh*64 + ri] = f1a;   f1p[nh*64 + ri + 8] = f1b;
        f2p[nh*64 + ri] = f2a;   f2p[nh*64 + ri + 8] = f2b;
    }
    __syncthreads();

    __half* Wt = (__half*)sp_;               // aliases hs (GEMM reads done)
#pragma unroll
    for (int nt = 0; nt < 4; nt++) {
#pragma unroll
        for (int e = 0; e < 4; e++) {
            const int col = nh*32 + nt*8 + tig*2 + (e & 1);
            const int kl = mt4*16 + gid + ((e >> 1) << 3);
            Wt[col*72 + kl] = __float2half(acc[nt][e]);
        }
    }
    __syncthreads();

    const int bb = i0 >> 11;
    const int kbase = i0 & (N_-1);
    {
        const int col = tid >> 2, seg = tid & 3;
        const __half* srcw = Wt + col*72 + seg*16;
        __half* dstw = g_WhT + (size_t)bb*FOUT*N_ + (size_t)col*N_ + kbase + seg*16;
        *(uint4*)dstw = *(const uint4*)srcw;
        *(uint4*)(dstw + 8) = *(const uint4*)(srcw + 8);
    }
    if (tid < 64) {
        g_f1[i0 + tid] = f1p[tid] + f1p[64 + tid];
        g_f2[i0 + tid] = f2p[tid] + f2p[64 + tid];
    }
}

// ---------------------------------------------------------------------------
__global__ void __launch_bounds__(256) scalars_kernel() {
    __shared__ float red[8];
    __shared__ float M2s;
    const int b = blockIdx.x, tid = threadIdx.x;
    const int base = b * N_;

    float m = -1e30f;
#pragma unroll
    for (int k = 0; k < 8; k++) m = fmaxf(m, g_f2[base + tid + k*256]);
#pragma unroll
    for (int o = 16; o > 0; o >>= 1) m = fmaxf(m, __shfl_xor_sync(0xffffffffu, m, o));
    if ((tid & 31) == 0) red[tid >> 5] = m;
    __syncthreads();
    if (tid == 0) {
        float mm = red[0];
#pragma unroll
        for (int i = 1; i < 8; i++) mm = fmaxf(mm, red[i]);
        M2s = mm;
    }
    __syncthreads();
    const float M2 = M2s;

#pragma unroll
    for (int k = 0; k < 8; k++) {
        const int node = base + tid + k*256;
        const float f1 = g_f1[node], f2 = g_f2[node];
        const float S = f1 + M2;
        const float mi = (S >= 0.f) ? S : 0.2f*S;
        g_E1p[node] = expf(f1 - mi);
        g_E1n[node] = expf(0.2f*f1 - mi);
        g_E2p[node] = expf(f2);
        g_E2n[node] = expf(0.2f*f2);
    }
}

// ---------------------------------------------------------------------------
// Main (R12 structure, Z via registers): CTA = (128 rows, batch, j-half).
// Z accumulated during P-build from the SAME rounded fp16 values (R11-proven
// numerics) -> ones-tile MMA deleted; all warps run 32 MMAs/stage (balanced).
// ---------------------------------------------------------------------------
__global__ void __launch_bounds__(256,2) gat_mma(const int* __restrict__ adj) {
    extern __shared__ __half smb[];
    const uint32_t sb = smem_u32(smb);
    const int tid = threadIdx.x;
    const int b  = blockIdx.y;
    const int sp = blockIdx.z;
    const int i0 = blockIdx.x * BM;
    const int js = sp * JCH;
    const int nodeBase = b * N_;

    const int rg = tid >> 4;          // P rows rg*8..+7
    const int cg = tid & 15;          // P cols cg*4..+3 (within BK)
    const int wid = tid >> 5, lane = tid & 31;
    const int gid = lane >> 2, tig = lane & 3;
    const int am = (wid & 3) * 32;    // warp m-offset (2 m16 tiles)
    const int nw = wid >> 2;          // warp n-half

    float e1p[8], e1n[8];
#pragma unroll
    for (int r = 0; r < 8; r++) {
        const int node = nodeBase + i0 + rg*8 + r;
        e1p[r] = g_E1p[node];
        e1n[r] = g_E1n[node];
    }

    // B staging: 64 rows x 128B; thread covers (row tid>>3, seg tid&7), 2 passes
    const int brow = tid >> 3, bseg = (tid & 7) * 8;
    const __half* bsrc = g_WhT + (size_t)b*FOUT*N_ + (size_t)brow*N_ + js + bseg;

#define CPB(S) do {                                                              \
        const uint32_t _bo = ((S)&1) ? OFF_B1 : OFF_B0;                          \
        cp16(sb + (_bo + brow*PSTRB + bseg)*2,        bsrc + (S)*BK);            \
        cp16(sb + (_bo + (brow+32)*PSTRB + bseg)*2,   bsrc + (size_t)32*N_ + (S)*BK); \
        CP_COMMIT();                                                             \
    } while (0)

    const int* adjB = adj + (size_t)b*N_*N_ + (size_t)(i0 + rg*8)*N_ + js + cg*4;
    int4 a4[8]; float4 p2v, n2v;

#define PF(S) do {                                                               \
        _Pragma("unroll")                                                        \
        for (int r = 0; r < 8; r++)                                              \
            a4[r] = __ldcs((const int4*)(adjB + (size_t)r*N_ + (S)*BK));         \
        const int _cn = nodeBase + js + (S)*BK + cg*4;                           \
        p2v = *(const float4*)(g_E2p + _cn);                                     \
        n2v = *(const float4*)(g_E2n + _cn);                                     \
    } while (0)

    CPB(0);
    PF(0);

    uint32_t aoff[2];
#pragma unroll
    for (int mt = 0; mt < 2; mt++)
        aoff[mt] = ((am + mt*16 + (lane & 7) + ((lane >> 3) & 1)*8)*PSTRB
                    + (lane >> 4)*8) * 2;

    float acc[2][4][4] = {};
    float zacc[8] = {};

    for (int s = 0; s < NST; s++) {
        const uint32_t pOff = (s & 1) ? OFF_P1 : OFF_P0;
        const float p2a[4] = {p2v.x, p2v.y, p2v.z, p2v.w};
        const float n2a[4] = {n2v.x, n2v.y, n2v.z, n2v.w};

        // ---- P build (fp16, values <= 1) + STS.64; Z from rounded values ----
#pragma unroll
        for (int r = 0; r < 8; r++) {
            const int am4[4] = {a4[r].x, a4[r].y, a4[r].z, a4[r].w};
            float pv[4];
#pragma unroll
            for (int c = 0; c < 4; c++) {
                const float v = fmaxf(e1p[r]*p2a[c], e1n[r]*n2a[c]);
                pv[c] = (am4[c] != 0) ? v : 0.f;
            }
            __half2 h01 = __floats2half2_rn(pv[0], pv[1]);
            __half2 h23 = __floats2half2_rn(pv[2], pv[3]);
            const float2 z01 = __half22float2(h01);
            const float2 z23 = __half22float2(h23);
            zacc[r] += (z01.x + z01.y) + (z23.x + z23.y);
            uint2 pk;
            pk.x = *reinterpret_cast<uint32_t*>(&h01);
            pk.y = *reinterpret_cast<uint32_t*>(&h23);
            *(uint2*)(smb + pOff + (rg*8 + r)*PSTRB + cg*4) = pk;
        }

        if (s + 1 < NST) PF(s + 1);     // issue adj LDG early

        CP_WAIT0();                     // B(s) landed
        __syncthreads();                // P(s)+B(s) visible; prev GEMM done
        if (s + 1 < NST) CPB(s + 1);

        // ---- GEMM: 4 kq x (2 ldmatrix + 4 nt) -- balanced, no ones tile ----
        const uint32_t pB = sb + pOff*2;
        const __half* Bs = smb + ((s & 1) ? OFF_B1 : OFF_B0);
#pragma unroll
        for (int kq = 0; kq < 4; kq++) {
            uint32_t A[2][4];
            LDMATRIX_X4(A[0], pB + aoff[0] + kq*32);
            LDMATRIX_X4(A[1], pB + aoff[1] + kq*32);
            const __half* Bk = Bs + kq*16 + tig*2;
#pragma unroll
            for (int nt = 0; nt < 4; nt++) {
                const int nrow = nw*32 + nt*8 + gid;
                const uint32_t b0 = *(const uint32_t*)(Bk + nrow*PSTRB);
                const uint32_t b1 = *(const uint32_t*)(Bk + nrow*PSTRB + 8);
                MMA_F16(acc[0][nt], A[0], b0, b1);
                MMA_F16(acc[1][nt], A[1], b0, b1);
            }
        }
    }

    // ---- Z reduce over cg (16 threads share a row set; lanes xor 1,2,4,8) ----
#pragma unroll
    for (int o = 1; o <= 8; o <<= 1)
#pragma unroll
        for (int r = 0; r < 8; r++)
            zacc[r] += __shfl_xor_sync(0xffffffffu, zacc[r], o);
    if (cg == 0) {
#pragma unroll
        for (int r = 0; r < 8; r++)
            g_Z[(size_t)sp*NNODE + nodeBase + i0 + rg*8 + r] = zacc[r];
    }

    // ---- store partials ----
    const size_t obase = ((size_t)sp*NNODE + nodeBase + i0) * FOUT;
#pragma unroll
    for (int mt = 0; mt < 2; mt++) {
        const int row = am + mt*16 + gid;
#pragma unroll
        for (int nt = 0; nt < 4; nt++) {
            const int col = nw*32 + nt*8 + tig*2;
            *(float2*)&g_acc[obase + (size_t)row*FOUT + col] =
                make_float2(acc[mt][nt][0], acc[mt][nt][1]);
            *(float2*)&g_acc[obase + (size_t)(row + 8)*FOUT + col] =
                make_float2(acc[mt][nt][2], acc[mt][nt][3]);
        }
    }
}

// ---------------------------------------------------------------------------
__global__ void __launch_bounds__(256) combine_kernel(float* __restrict__ out) {
    const int idx = blockIdx.x * 256 + threadIdx.x;   // 0 .. NNODE*8-1
    const int node = idx >> 3;
    const int f8 = (idx & 7) * 8;
    float s0x=0.f,s0y=0.f,s0z=0.f,s0w=0.f;
    float s1x=0.f,s1y=0.f,s1z=0.f,s1w=0.f;
    float z = 0.f;
#pragma unroll
    for (int sp = 0; sp < SPLIT; sp++) {
        const float* base = &g_acc[((size_t)sp*NNODE + node)*FOUT + f8];
        const float4 v0 = *(const float4*)base;
        const float4 v1 = *(const float4*)(base + 4);
        s0x += v0.x; s0y += v0.y; s0z += v0.z; s0w += v0.w;
        s1x += v1.x; s1y += v1.y; s1z += v1.z; s1w += v1.w;
        z += g_Z[(size_t)sp*NNODE + node];
    }
    const float inv = 1.0f / z;
    float* op = &out[(size_t)node*FOUT + f8];
    *(float4*)op       = make_float4(s0x*inv, s0y*inv, s0z*inv, s0w*inv);
    *(float4*)(op + 4) = make_float4(s1x*inv, s1y*inv, s1z*inv, s1w*inv);
}

// ---------------------------------------------------------------------------
extern "C" void kernel_launch(void* const* d_in, const int* in_sizes, int n_in,
                              void* d_out, int out_size) {
    const float* h   = (const float*)d_in[0];
    const float* W   = (const float*)d_in[1];
    const float* a   = (const float*)d_in[2];
    const int*   adj = (const int*)d_in[3];
    float* out = (float*)d_out;

    cudaFuncSetAttribute(prep_mma, cudaFuncAttributeMaxDynamicSharedMemorySize, PREP_SMEM);
    prep_mma<<<NNODE/64, 256, PREP_SMEM>>>(h, W, a);

    scalars_kernel<<<B_, 256>>>();

    cudaFuncSetAttribute(gat_mma, cudaFuncAttributeMaxDynamicSharedMemorySize, GAT_SMEM);
    dim3 grid(N_/BM, B_, SPLIT);
    gat_mma<<<grid, 256, GAT_SMEM>>>(adj);

    combine_kernel<<<(NNODE*8)/256, 256>>>(out);
}